// round 17
// baseline (speedup 1.0000x reference)
#include <cuda_runtime.h>
#include <cuda_bf16.h>
#include <cstdint>

#if defined(__CUDA_ARCH_FEAT_SM103_ALL) || defined(__CUDA_ARCH_FEAT_SM100_ALL) || \
    defined(__CUDA_ARCH_FEAT_SM101_ALL) || defined(__CUDA_ARCH_SPECIFIC__)
#define TC_OK 1
#else
#define TC_OK 0
#endif

#define NVOX 150000
#define CCH 256
#define NTILES 1172
#define NPAIRS 586            // 2 tiles per CTA
#define NSLOTS 36

// SMEM: 3 stages {A0 16K @0, A1 16K @16K, B 32K @32K}
#define SMEM_TMEMPTR 0
#define SMEM_FREE    16        // 3 x 8B (stage free <- MMA commit)
#define SMEM_STFULL  40        // 3 x 8B (stage bulks arrived, tx)
#define SMEM_AXDONE  64
#define SMEM_GB      128
#define SMEM_STG     8192
#define STG_BYTES    65536
#define SMEM_BYTES   (8192 + 3 * STG_BYTES)   // 204800

#define MMA_IDESC 0x08400490u  // f32 acc, bf16 x bf16, M=128 N=256

__device__ __align__(16) unsigned char g_Bimg[3 * 12 * 32768];
// tile-major pre-swizzled bf16 feats: [NTILES][4 K64 quarters][128 rows x 128B SW128]
__device__ __align__(16) unsigned char g_featsTile[(size_t)NTILES * 65536];

#define PREP_W_IDS (3 * 196608)
#define PREP_F_IDS ((NVOX * CCH) / 16)
#define PREP_BLOCKS ((PREP_W_IDS + PREP_F_IDS + 255) / 256)

__device__ __forceinline__ uint32_t smem_u32(const void* p) {
    uint32_t a;
    asm("{ .reg .u64 t; cvta.to.shared.u64 t, %1; cvt.u32.u64 %0, t; }" : "=r"(a) : "l"(p));
    return a;
}
#define SW128(o) ((o) ^ (((o) >> 3) & 0x70))
static constexpr uint64_t DESC_BASE =
    (uint64_t(2) << 61) | (uint64_t(1) << 46) | (uint64_t(64) << 32) | (uint64_t(1) << 16);
#define MAKE_DESC(a) (DESC_BASE | ((uint64_t)((a) >> 4) & 0x3FFF))
__device__ __forceinline__ uint32_t pack_bf16x2(float a, float b) {
    __nv_bfloat162 h = __floats2bfloat162_rn(a, b);
    return *reinterpret_cast<uint32_t*>(&h);
}

#if TC_OK
__device__ __forceinline__ uint32_t elect_one() {
    uint32_t p;
    asm volatile("{ .reg .pred p; elect.sync _|p, 0xFFFFFFFF; selp.b32 %0, 1, 0, p; }" : "=r"(p));
    return p;
}
#define TC_ALLOC(sa, n)  asm volatile("tcgen05.alloc.cta_group::1.sync.aligned.shared::cta.b32 [%0], %1;" :: "r"((uint32_t)(sa)), "r"((uint32_t)(n)) : "memory")
#define TC_DEALLOC(t, n) asm volatile("tcgen05.dealloc.cta_group::1.sync.aligned.b32 %0, %1;" :: "r"(t), "r"((uint32_t)(n)))
#define TC_RELINQ()      asm volatile("tcgen05.relinquish_alloc_permit.cta_group::1.sync.aligned;")
#define TC_COMMIT(m)     asm volatile("tcgen05.commit.cta_group::1.mbarrier::arrive::one.shared::cluster.b64 [%0];" :: "r"((uint32_t)(m)) : "memory")
#define TC_WAIT_LD()     asm volatile("tcgen05.wait::ld.sync.aligned;" ::: "memory")
#define TC_FENCE_BEFORE() asm volatile("tcgen05.fence::before_thread_sync;" ::: "memory")
#define TC_FENCE_AFTER()  asm volatile("tcgen05.fence::after_thread_sync;" ::: "memory")
#define FENCE_ASYNC()    asm volatile("fence.proxy.async.shared::cta;" ::: "memory")
#define MBAR_INIT(m, c)  asm volatile("mbarrier.init.shared.b64 [%0], %1;" :: "r"((uint32_t)(m)), "r"((uint32_t)(c)) : "memory")
#define MBAR_TX(m, b)    asm volatile("mbarrier.arrive.expect_tx.shared.b64 _, [%0], %1;" :: "r"((uint32_t)(m)), "r"((uint32_t)(b)) : "memory")
#define MBAR_WAIT(m, ph) do { \
    uint32_t _m = (uint32_t)(m), _p = (uint32_t)(ph), _d; \
    asm volatile("{ .reg .pred p; mbarrier.try_wait.parity.acquire.cta.shared::cta.b64 p, [%1], %2; selp.b32 %0, 1, 0, p; }" \
        : "=r"(_d) : "r"(_m), "r"(_p) : "memory"); \
    if (!_d) asm volatile("{ .reg .pred P1; WL_%=: mbarrier.try_wait.parity.acquire.cta.shared::cta.b64 P1, [%0], %1, 0x989680; @P1 bra.uni WD_%=; bra.uni WL_%=; WD_%=: }" \
        :: "r"(_m), "r"(_p) : "memory"); \
} while (0)
#define TC_LD16(r, ta) asm volatile( \
    "tcgen05.ld.sync.aligned.32x32b.x16.b32 {%0,%1,%2,%3,%4,%5,%6,%7,%8,%9,%10,%11,%12,%13,%14,%15}, [%16];" \
    : "=r"((r)[0]), "=r"((r)[1]), "=r"((r)[2]), "=r"((r)[3]), "=r"((r)[4]), "=r"((r)[5]), "=r"((r)[6]), "=r"((r)[7]), \
      "=r"((r)[8]), "=r"((r)[9]), "=r"((r)[10]), "=r"((r)[11]), "=r"((r)[12]), "=r"((r)[13]), "=r"((r)[14]), "=r"((r)[15]) : "r"(ta))
__device__ __forceinline__ void mma_f16_ss(uint32_t d, uint64_t ad, uint64_t bd,
                                           uint32_t idesc, uint32_t en) {
    asm volatile("{ .reg .pred p; setp.ne.u32 p, %5, 0; "
                 "tcgen05.mma.cta_group::1.kind::f16 [%0], %1, %2, %3, {%4,%4,%4,%4}, p; }"
                 :: "r"(d), "l"(ad), "l"(bd), "r"(idesc), "r"(0u), "r"(en) : "memory");
}
#define CPA16(dst, src)  asm volatile("cp.async.cg.shared.global [%0], [%1], 16;" :: "r"((uint32_t)(dst)), "l"(src) : "memory")
#define CPA_COMMIT()     asm volatile("cp.async.commit_group;" ::: "memory")
#define CPA_WAIT0()      asm volatile("cp.async.wait_group 0;" ::: "memory")
#define CP_BULK(dst, src, b, m) asm volatile( \
    "cp.async.bulk.shared::cluster.global.mbarrier::complete_tx::bytes [%0], [%1], %2, [%3];" \
    :: "r"((uint32_t)(dst)), "l"(src), "r"((uint32_t)(b)), "r"((uint32_t)(m)) : "memory")
#endif

__global__ void prep_all_kernel(const float* __restrict__ w1, const float* __restrict__ w2,
                                const float* __restrict__ w3, const float* __restrict__ feats) {
#if TC_OK
    int id = blockIdx.x * 256 + threadIdx.x;
    if (id < PREP_W_IDS) {
        int axis = id / 196608;
        int r = id - axis * 196608;
        const float* w = (axis == 0) ? w1 : ((axis == 1) ? w2 : w3);
        float v = w[r];
        int kk = (r >> 16) * 256 + ((r >> 8) & 255);
        int off = (r & 255) * 128 + (kk & 63) * 2;
        *reinterpret_cast<__nv_bfloat16*>(g_Bimg + (axis * 12 + (kk >> 6)) * 32768 + SW128(off)) =
            __float2bfloat16(v);
    } else {
        int t = id - PREP_W_IDS;
        if (t >= PREP_F_IDS) return;
        int v = t >> 4, c0 = (t & 15) << 4;
        const float4* src = reinterpret_cast<const float4*>(feats) + (size_t)t * 4;
        float4 a = src[0], b = src[1], c = src[2], d = src[3];
        uint4 r0 = make_uint4(pack_bf16x2(a.x, a.y), pack_bf16x2(a.z, a.w),
                              pack_bf16x2(b.x, b.y), pack_bf16x2(b.z, b.w));
        uint4 r1 = make_uint4(pack_bf16x2(c.x, c.y), pack_bf16x2(c.z, c.w),
                              pack_bf16x2(d.x, d.y), pack_bf16x2(d.z, d.w));
        size_t base = (size_t)(v >> 7) * 65536 + (size_t)(c0 >> 6) * 16384;
        uint32_t off = (uint32_t)((v & 127) * 128 + (c0 & 63) * 2);
        *reinterpret_cast<uint4*>(g_featsTile + base + SW128(off)) = r0;
        *reinterpret_cast<uint4*>(g_featsTile + base + SW128(off + 16)) = r1;
    }
#endif
}

__global__ __launch_bounds__(512, 1)
void recon_main_kernel(const float* __restrict__ feats,
                       const float* __restrict__ w1, const float* __restrict__ w2,
                       const float* __restrict__ w3,
                       const float* __restrict__ g1, const float* __restrict__ b1,
                       const float* __restrict__ g2, const float* __restrict__ b2,
                       const float* __restrict__ g3, const float* __restrict__ b3,
                       const int* __restrict__ nx, const int* __restrict__ ny,
                       const int* __restrict__ nz, float* __restrict__ out) {
    extern __shared__ __align__(1024) unsigned char smem[];
    int tid = threadIdx.x, warp = tid >> 5, lane = tid & 31;
    int m0 = blockIdx.x * 256;             // first row of tile pair
    // A loader: tile trow = tid>>8; row = (tid&255)>>1; aseg = tid&1 (owns 64B)
    int trow = tid >> 8;
    int arow = (tid & 255) >> 1;
    int aseg = tid & 1;
    int agm = m0 + trow * 128 + arow;
    bool rowvalid = agm < NVOX;
    // epilogue: warp w -> rows (w&3)*32+lane, cols [(w>>2)*64, +64), both tiles
    int erow = (warp & 3) * 32 + lane, colb = (warp >> 2) * 64;
    const float RS = rsqrtf(1.00001f);

#if TC_OK
    uint32_t sb = smem_u32(smem);
    const int bmap[12] = {4, 5, 6, 7, 0, 1, 2, 3, 8, 9, 10, 11};

    int nidx[6];   // [axis][side] for this thread's row in its tile
    {
        const int* nbs[3] = {nx, ny, nz};
#pragma unroll
        for (int a = 0; a < 3; a++) {
            nidx[a * 2 + 0] = rowvalid ? __ldg(&nbs[a][agm * 3 + 0]) : -1;
            nidx[a * 2 + 1] = rowvalid ? __ldg(&nbs[a][agm * 3 + 2]) : -1;
        }
    }
    float* gb = reinterpret_cast<float*>(smem + SMEM_GB);
    if (tid < 256) {
        gb[tid] = g1[tid]; gb[256 + tid] = b1[tid];
        gb[512 + tid] = g2[tid]; gb[768 + tid] = b2[tid];
        gb[1024 + tid] = g3[tid]; gb[1280 + tid] = b3[tid];
    }
    if (warp == 0) TC_ALLOC(sb + SMEM_TMEMPTR, 512);
    if (tid == 0) {
#pragma unroll
        for (int i = 0; i < 3; i++) {
            MBAR_INIT(sb + SMEM_FREE + 8 * i, 1);
            MBAR_INIT(sb + SMEM_STFULL + 8 * i, 1);
        }
        MBAR_INIT(sb + SMEM_AXDONE, 1);
    }
    // this thread's 4 swizzled 16B offsets within its tile's A region
    uint32_t aoff[4];
#pragma unroll
    for (int i = 0; i < 4; i++)
        aoff[i] = SW128((uint32_t)(arow * 128 + aseg * 64 + i * 16));
    uint32_t a_tile_rel = (uint32_t)(trow * 16384);
    unsigned pvm = 0;
    __syncthreads();
    uint32_t tmem;
    asm volatile("ld.shared.b32 %0, [%1];" : "=r"(tmem) : "r"(sb + SMEM_TMEMPTR));

    auto produce = [&](int p) {
        int st = p % 3;
        if (p >= 3)   // freed by commit(p-3), issued 2 iterations earlier
            MBAR_WAIT(sb + SMEM_FREE + 8 * st, ((p / 3) - 1) & 1);
        int axis_p = p / 12, sl = p - axis_p * 12;
        uint32_t base = sb + SMEM_STG + (uint32_t)st * STG_BYTES;
        bool dense = sl < 4;
        if (warp == 0 && elect_one()) {
            uint32_t m = sb + SMEM_STFULL + 8 * st;
            const unsigned char* bsrc = g_Bimg + (size_t)(axis_p * 12 + bmap[sl]) * 32768;
            if (dense) {
                MBAR_TX(m, 65536u);
                CP_BULK(base, g_featsTile + (size_t)(2 * blockIdx.x) * 65536 + (size_t)sl * 16384, 16384u, m);
                CP_BULK(base + 16384, g_featsTile + (size_t)(2 * blockIdx.x + 1) * 65536 + (size_t)sl * 16384, 16384u, m);
                CP_BULK(base + 32768, bsrc, 32768u, m);
            } else {
                MBAR_TX(m, 32768u);
                CP_BULK(base + 32768, bsrc, 32768u, m);
            }
        }
        if (!dense) {
            int prev = p - 3;
            bool prev_dense = (prev % 12) < 4;
            uint32_t adst = base + a_tile_rel;
            if (prev_dense || (pvm & (1u << st))) {
                uint4 z = make_uint4(0, 0, 0, 0);
#pragma unroll
                for (int i = 0; i < 4; i++)
                    *reinterpret_cast<uint4*>(smem + SMEM_STG + st * STG_BYTES + a_tile_rel + aoff[i]) = z;
                pvm &= ~(1u << st);
            }
            int side = (sl - 4) >> 2, q = sl & 3;
            int v = nidx[axis_p * 2 + side];
            if (v >= 0) {
                const unsigned char* srcb = g_featsTile + (size_t)(v >> 7) * 65536 + (size_t)q * 16384;
                uint32_t sbase = (uint32_t)((v & 127) * 128 + aseg * 64);
#pragma unroll
                for (int i = 0; i < 4; i++)
                    CPA16(adst + aoff[i], srcb + SW128(sbase + i * 16));
                pvm |= 1u << st;
            }
        }
        CPA_COMMIT();
    };

    produce(0);
    for (int g = 0; g < NSLOTS; g++) {
        int axis_g = g / 12, sl = g - axis_g * 12, st = g % 3;

        CPA_WAIT0();       // slot g's sparse loads landed (issued prev iter)
        FENCE_ASYNC();
        __syncthreads();   // also orders prev epilogue TMEM reads before new MMAs

        if (warp == 0 && elect_one()) {
            MBAR_WAIT(sb + SMEM_STFULL + 8 * st, (g / 3) & 1);
            if (sl == 0) TC_FENCE_AFTER();
            uint32_t base = sb + SMEM_STG + (uint32_t)st * STG_BYTES;
            uint64_t ad0 = MAKE_DESC(base);
            uint64_t ad1 = MAKE_DESC(base + 16384);
            uint64_t bd = MAKE_DESC(base + 32768);
#pragma unroll
            for (int k = 0; k < 4; k++)
                mma_f16_ss(tmem, ad0 + k * 2, bd + k * 2, MMA_IDESC,
                           (uint32_t)((sl > 0) || (k > 0)));
#pragma unroll
            for (int k = 0; k < 4; k++)
                mma_f16_ss(tmem + 256, ad1 + k * 2, bd + k * 2, MMA_IDESC,
                           (uint32_t)((sl > 0) || (k > 0)));
            TC_COMMIT(sb + SMEM_FREE + 8 * st);
            if (sl == 11) TC_COMMIT(sb + SMEM_AXDONE);
        }

        if (g + 1 < NSLOTS) produce(g + 1);

        if (sl == 11) {   // axis epilogue: accumulate into out (gmem)
            MBAR_WAIT(sb + SMEM_AXDONE, axis_g & 1);
            TC_FENCE_AFTER();
            const float* gptr = gb + axis_g * 512;
#pragma unroll
            for (int t = 0; t < 2; t++) {
                int egm = m0 + t * 128 + erow;
                bool ok = egm < NVOX;
                float* orow = out + (size_t)egm * CCH + colb;
                const float* frow = feats + (size_t)egm * CCH + colb;
#pragma unroll
                for (int i = 0; i < 4; i++) {
                    uint32_t tt[16];
                    TC_LD16(tt, tmem + (t << 8) + colb + i * 16);
                    TC_WAIT_LD();
                    float sig[16];
#pragma unroll
                    for (int j = 0; j < 16; j++) {
                        int c = colb + i * 16 + j;
                        float v = fmaf(__uint_as_float(tt[j]), gptr[c] * RS, gptr[256 + c]);
                        sig[j] = 1.0f / (1.0f + __expf(-v));
                    }
                    if (ok) {
                        float4* o4 = reinterpret_cast<float4*>(orow + i * 16);
                        if (axis_g == 0) {
#pragma unroll
                            for (int q = 0; q < 4; q++)
                                o4[q] = make_float4(sig[q * 4], sig[q * 4 + 1],
                                                    sig[q * 4 + 2], sig[q * 4 + 3]);
                        } else if (axis_g == 1) {
#pragma unroll
                            for (int q = 0; q < 4; q++) {
                                float4 pv = o4[q];
                                o4[q] = make_float4(pv.x + sig[q * 4], pv.y + sig[q * 4 + 1],
                                                    pv.z + sig[q * 4 + 2], pv.w + sig[q * 4 + 3]);
                            }
                        } else {
                            const float4* f4 = reinterpret_cast<const float4*>(frow + i * 16);
#pragma unroll
                            for (int q = 0; q < 4; q++) {
                                float4 pv = o4[q];
                                float4 fv = f4[q];
                                o4[q] = make_float4((pv.x + sig[q * 4]) * fv.x,
                                                    (pv.y + sig[q * 4 + 1]) * fv.y,
                                                    (pv.z + sig[q * 4 + 2]) * fv.z,
                                                    (pv.w + sig[q * 4 + 3]) * fv.w);
                            }
                        }
                    }
                }
            }
            TC_FENCE_BEFORE();
        }
    }

    __syncthreads();
    if (warp == 0) { TC_RELINQ(); TC_DEALLOC(tmem, 512); }

#else
    // Minimal correct fallback for the portable PTX pass (never runs; the
    // sm_103a cubin is preferred at load time).
    for (int t = 0; t < 2; t++) {
        int egm = m0 + t * 128 + erow;
        if (egm >= NVOX) continue;
        const int* nbs[3] = {nx, ny, nz};
        const float* ws[3] = {w1, w2, w3};
        const float* gs[3] = {g1, g2, g3};
        const float* bs[3] = {b1, b2, b3};
        float s[64];
        for (int i = 0; i < 64; i++) s[i] = 0.0f;
        for (int a = 0; a < 3; a++) {
            float y[64];
            for (int i = 0; i < 64; i++) y[i] = 0.0f;
            for (int tp = 0; tp < 3; tp++) {
                int idx = __ldg(&nbs[a][egm * 3 + tp]);
                if (idx < 0) continue;
                for (int k = 0; k < CCH; k++) {
                    float fv = __ldg(&feats[(size_t)idx * CCH + k]);
                    const float* wr = ws[a] + (size_t)tp * 65536 + (size_t)k * 256 + colb;
                    for (int c = 0; c < 64; c++) y[c] = fmaf(fv, __ldg(&wr[c]), y[c]);
                }
            }
            for (int c = 0; c < 64; c++) {
                float v = fmaf(y[c], __ldg(&gs[a][colb + c]) * RS, __ldg(&bs[a][colb + c]));
                s[c] += 1.0f / (1.0f + __expf(-v));
            }
        }
        for (int c = 0; c < 64; c++)
            out[(size_t)egm * CCH + colb + c] = s[c] * feats[(size_t)egm * CCH + colb + c];
    }
#endif
}

extern "C" void kernel_launch(void* const* d_in, const int* in_sizes, int n_in,
                              void* d_out, int out_size) {
    const float* feats = (const float*)d_in[0];
    const float* w1 = (const float*)d_in[1];
    const float* w2 = (const float*)d_in[2];
    const float* w3 = (const float*)d_in[3];
    const float* g1 = (const float*)d_in[4];
    const float* b1 = (const float*)d_in[5];
    const float* g2 = (const float*)d_in[6];
    const float* b2 = (const float*)d_in[7];
    const float* g3 = (const float*)d_in[8];
    const float* b3 = (const float*)d_in[9];
    const int* nx = (const int*)d_in[10];
    const int* ny = (const int*)d_in[11];
    const int* nz = (const int*)d_in[12];
    float* out = (float*)d_out;

    cudaFuncSetAttribute(recon_main_kernel,
                         cudaFuncAttributeMaxDynamicSharedMemorySize, SMEM_BYTES);
    prep_all_kernel<<<PREP_BLOCKS, 256>>>(w1, w2, w3, feats);
    recon_main_kernel<<<NPAIRS, 512, SMEM_BYTES>>>(feats, w1, w2, w3,
                                                   g1, b1, g2, b2, g3, b3,
                                                   nx, ny, nz, out);
}